// round 5
// baseline (speedup 1.0000x reference)
#include <cuda_runtime.h>
#include <cstdint>

#define NBS 100000
#define NGS 20000
#define EL  1000000
#define EX  200000

#define BUSB ((NBS + 127) / 128)   // 782 blocks, 128 rows each
#define GENB ((NGS + 127) / 128)   // 157

// ---------------- scratch (static device globals; no allocation) ----------------
__device__ float g_hb[NBS * 64];
__device__ float g_hg[NGS * 64];
__device__ float g_aggL[NBS * 64];   // sum of hb over line edges, at bus dst
__device__ float g_aggG[NBS * 64];   // sum of hg over g2b edges, at bus dst
__device__ float g_aggB[NGS * 64];   // sum of hb over b2g edges, at gen dst
__device__ float g_invL[NBS], g_invG[NBS], g_invB[NGS];
__device__ int   g_cntL[NBS], g_cntG[NBS], g_cntB[NGS];
__device__ float g_pool[128];

// ---------------- f32x2 helpers ----------------
__device__ __forceinline__ unsigned long long packf2(float v) {
    unsigned long long r;
    asm("mov.b64 %0, {%1, %1};" : "=l"(r) : "f"(v));
    return r;
}
__device__ __forceinline__ unsigned long long packf2b(float a, float b) {
    unsigned long long r;
    asm("mov.b64 %0, {%1, %2};" : "=l"(r) : "f"(a), "f"(b));
    return r;
}
__device__ __forceinline__ void fma2(unsigned long long& acc,
                                     unsigned long long a, unsigned long long b) {
    asm("fma.rn.f32x2 %0, %1, %2, %0;" : "+l"(acc) : "l"(a), "l"(b));
}
__device__ __forceinline__ void lds2(unsigned long long& w0, unsigned long long& w1,
                                     unsigned addr) {
    asm volatile("ld.shared.v2.u64 {%0, %1}, [%2];"
                 : "=l"(w0), "=l"(w1) : "r"(addr));
}
__device__ __forceinline__ void unpackf2(unsigned long long v, float& a, float& b) {
    asm("mov.b64 {%0, %1}, %2;" : "=f"(a), "=f"(b) : "l"(v));
}

// ---------------- in-degree counts (cnt arrays are zero: module init /
// re-zeroed by k_inv each call, so graph replays stay correct) ----------------
__global__ void k_count_all(const int* __restrict__ ldst,
                            const int* __restrict__ gd,
                            const int* __restrict__ bd) {
    int i = blockIdx.x * blockDim.x + threadIdx.x;
    if (i < EL) atomicAdd(&g_cntL[ldst[i]], 1);
    if (i < EX) { atomicAdd(&g_cntG[gd[i]], 1); atomicAdd(&g_cntB[bd[i]], 1); }
}

// ---------------- inv + re-zero counters + zero pool (one launch) ----------------
__global__ void k_inv() {
    int i = blockIdx.x * blockDim.x + threadIdx.x;
    if (i < NBS) {
        g_invL[i] = 1.f / (float)max(g_cntL[i], 1);
        g_invG[i] = 1.f / (float)max(g_cntG[i], 1);
        g_cntL[i] = 0; g_cntG[i] = 0;
    }
    if (i < NGS) {
        g_invB[i] = 1.f / (float)max(g_cntB[i], 1);
        g_cntB[i] = 0;
    }
    if (i < 128) g_pool[i] = 0.f;
}

// ---------------- unified raw-feature edge scatter (all 3 edge types) ----------------
// 16 threads/edge: gather h[src] (float4 each) and vector-RED into agg[dst].
// h pointers == nullptr select the internal layer-1 buffers.
__global__ void k_scatter_all(const float* hb, const float* hg,
                              const int* __restrict__ ls, const int* __restrict__ ldst,
                              const int* __restrict__ gs, const int* __restrict__ gd,
                              const int* __restrict__ bs, const int* __restrict__ bd)
{
    int tid = blockIdx.x * 256 + threadIdx.x;
    int e = tid >> 4;
    int q = tid & 15;
    const float* hbp = hb ? hb : (const float*)g_hb;
    const float* hgp = hg ? hg : (const float*)g_hg;

    const float4* srcv;
    float* agg;
    int s, d;
    if (e < EL) {
        s = __ldg(&ls[e]); d = __ldg(&ldst[e]);
        srcv = (const float4*)hbp; agg = g_aggL;
    } else if (e < EL + EX) {
        int e2 = e - EL;
        s = __ldg(&gs[e2]); d = __ldg(&gd[e2]);
        srcv = (const float4*)hgp; agg = g_aggG;
    } else {
        int e2 = e - EL - EX;
        s = __ldg(&bs[e2]); d = __ldg(&bd[e2]);
        srcv = (const float4*)hbp; agg = g_aggB;
    }
    float4 v = srcv[(size_t)s * 16 + q];
    float* p = agg + (size_t)d * 64 + q * 4;
    asm volatile("red.global.add.v4.f32 [%0], {%1, %2, %3, %4};"
                 :: "l"(p), "f"(v.x), "f"(v.y), "f"(v.z), "f"(v.w) : "memory");
}

// ---------------- unified fused update (bus + gen), f32x2 GEMM, 2 threads/row ----
// bus: new_hb = relu(hb@Wsb + (aggL*invL)@Wl + (aggG*invG)@Wg2b + bsb)
// gen: new_hg = relu(hg@Wsg + (aggB*invB)@Wb2g + bsg)
// Each thread computes 32 of 64 output cols (half = t&1) -> acc fits in 32 regs,
// allowing 3 blocks/SM (6 warps/SMSP) to hide LDS latency.
// Also re-zeroes consumed agg rows (invariant for next scatter / next call).
__global__ void __launch_bounds__(256, 3) k_fused(
    const float* hbin, const float* hgin,
    const float* __restrict__ Wsb, const float* __restrict__ Wl,
    const float* __restrict__ Wg2b, const float* __restrict__ bsb,
    const float* __restrict__ Wsg, const float* __restrict__ Wb2g,
    const float* __restrict__ bsg)
{
    __shared__ __align__(16) float sW[192 * 64];
    __shared__ __align__(16) float sb[64];
    int t = threadIdx.x;
    bool bus = blockIdx.x < BUSB;

    if (bus) {
        for (int idx = t; idx < 4096; idx += 256) {
            sW[idx]        = Wsb[idx];
            sW[4096 + idx] = Wl[idx];
            sW[8192 + idx] = Wg2b[idx];
        }
        if (t < 64) sb[t] = bsb[t];
    } else {
        for (int idx = t; idx < 4096; idx += 256) {
            sW[idx]        = Wsg[idx];
            sW[4096 + idx] = Wb2g[idx];
        }
        if (t < 64) sb[t] = bsg[t];
    }
    __syncthreads();
    unsigned swb = (unsigned)__cvta_generic_to_shared(sW);

    int half = t & 1;          // which 32-column half this thread owns
    int rid  = t >> 1;         // 0..127 row within block
    int row = (bus ? blockIdx.x : blockIdx.x - BUSB) * 128 + rid;
    bool valid = row < (bus ? NBS : NGS);
    int r = valid ? row : 0;

    const float* hsrc = bus ? (hbin ? hbin : (const float*)g_hb)
                            : (hgin ? hgin : (const float*)g_hg);
    const float* hp = hsrc + (size_t)r * 64;
    float* agg1 = (bus ? g_aggL : g_aggB) + (size_t)r * 64;
    float* agg2 = g_aggG + (size_t)r * 64;  // only used by bus path
    float sc1 = bus ? g_invL[r] : g_invB[r];
    float sc2 = bus ? g_invG[r] : 0.f;
    int nkc = valid ? (bus ? 24 : 16) : 0;  // chunks of 8 k-values

    unsigned cb = swb + (unsigned)half * 128;   // this thread's column half

    unsigned long long acc[16];
#pragma unroll
    for (int g = 0; g < 8; g++) {
        acc[2 * g]     = packf2b(sb[half * 32 + 4 * g],     sb[half * 32 + 4 * g + 1]);
        acc[2 * g + 1] = packf2b(sb[half * 32 + 4 * g + 2], sb[half * 32 + 4 * g + 3]);
    }

    for (int kc = 0; kc < nkc; kc++) {
        const float4* s4;
        float sc;
        if (kc < 8)       { s4 = (const float4*)hp   + kc * 2;        sc = 1.f; }
        else if (kc < 16) { s4 = (const float4*)agg1 + (kc - 8) * 2;  sc = sc1; }
        else              { s4 = (const float4*)agg2 + (kc - 16) * 2; sc = sc2; }

        float4 v0 = s4[0], v1 = s4[1];
        float xc[8];
        xc[0] = v0.x * sc; xc[1] = v0.y * sc; xc[2] = v0.z * sc; xc[3] = v0.w * sc;
        xc[4] = v1.x * sc; xc[5] = v1.y * sc; xc[6] = v1.z * sc; xc[7] = v1.w * sc;

        unsigned a0 = cb + (unsigned)kc * 8 * 256;
#pragma unroll
        for (int kk = 0; kk < 8; kk++) {
            unsigned long long xx = packf2(xc[kk]);
            unsigned a = a0 + kk * 256;
#pragma unroll
            for (int g = 0; g < 8; g++) {
                unsigned long long w0, w1;
                lds2(w0, w1, a + g * 16);
                fma2(acc[2 * g],     xx, w0);
                fma2(acc[2 * g + 1], xx, w1);
            }
        }
    }

    if (valid) {
        // restore zeroed aggregation rows (this thread's half)
        float4 z = make_float4(0.f, 0.f, 0.f, 0.f);
        float4* a1 = (float4*)agg1 + half * 8;
#pragma unroll
        for (int i = 0; i < 8; i++) a1[i] = z;
        if (bus) {
            float4* a2 = (float4*)agg2 + half * 8;
#pragma unroll
            for (int i = 0; i < 8; i++) a2[i] = z;
        }
        float4* outr = (float4*)((bus ? g_hb : g_hg) + (size_t)row * 64) + half * 8;
#pragma unroll
        for (int g = 0; g < 8; g++) {
            float4 o;
            unpackf2(acc[2 * g],     o.x, o.y);
            unpackf2(acc[2 * g + 1], o.z, o.w);
            o.x = fmaxf(o.x, 0.f); o.y = fmaxf(o.y, 0.f);
            o.z = fmaxf(o.z, 0.f); o.w = fmaxf(o.w, 0.f);
            outr[g] = o;
        }
    }
}

// ---------------- sum pooling (bus + gen in one launch) ----------------
__global__ void k_pool_all() {
    bool bus = blockIdx.x < 240;
    const float* h = bus ? g_hb : g_hg;
    int n = bus ? NBS : NGS;
    int obase = bus ? 0 : 64;
    int bid = bus ? blockIdx.x : blockIdx.x - 240;
    int nb  = bus ? 240 : 60;

    int col = threadIdx.x & 63, grp = threadIdx.x >> 6;
    float s = 0.f;
    for (int r = bid * 4 + grp; r < n; r += nb * 4)
        s += h[(size_t)r * 64 + col];
    __shared__ float sh[256];
    sh[threadIdx.x] = s;
    __syncthreads();
    if (grp == 0)
        atomicAdd(&g_pool[obase + col],
                  sh[col] + sh[col + 64] + sh[col + 128] + sh[col + 192]);
}

// ---------------- MLP head ----------------
__global__ void k_head(const float* __restrict__ W_h, const float* __restrict__ b_h,
                       const float* __restrict__ W_o, const float* __restrict__ b_o,
                       float* __restrict__ out)
{
    __shared__ float sg[128], st[64];
    int t = threadIdx.x;   // 128 threads
    sg[t] = g_pool[t];
    __syncthreads();
    if (t < 64) {
        float a = b_h[t];
#pragma unroll
        for (int i = 0; i < 128; i++) a += sg[i] * W_h[i * 64 + t];
        st[t] = fmaxf(a, 0.f);
    }
    __syncthreads();
    if (t < 16) {
        float o = b_o[t];
#pragma unroll
        for (int j = 0; j < 64; j++) o += st[j] * W_o[j * 16 + t];
        out[t] = o;
    }
}

// ---------------- launch ----------------
extern "C" void kernel_launch(void* const* d_in, const int* in_sizes, int n_in,
                              void* d_out, int out_size)
{
    const float* x_bus   = (const float*)d_in[0];
    const float* x_gen   = (const float*)d_in[1];
    const int* line_src  = (const int*)d_in[2];
    const int* line_dst  = (const int*)d_in[3];
    const int* g2b_src   = (const int*)d_in[4];
    const int* g2b_dst   = (const int*)d_in[5];
    const int* b2g_src   = (const int*)d_in[6];
    const int* b2g_dst   = (const int*)d_in[7];
    const float* Wsb[2]  = { (const float*)d_in[8],  (const float*)d_in[15] };
    const float* Wsg[2]  = { (const float*)d_in[9],  (const float*)d_in[16] };
    const float* Wl[2]   = { (const float*)d_in[10], (const float*)d_in[17] };
    const float* Wg2b[2] = { (const float*)d_in[11], (const float*)d_in[18] };
    const float* Wb2g[2] = { (const float*)d_in[12], (const float*)d_in[19] };
    const float* bsb[2]  = { (const float*)d_in[13], (const float*)d_in[20] };
    const float* bsg[2]  = { (const float*)d_in[14], (const float*)d_in[21] };
    const float* W_h = (const float*)d_in[22];
    const float* b_h = (const float*)d_in[23];
    const float* W_o = (const float*)d_in[24];
    const float* b_o = (const float*)d_in[25];

    const int SCAT_BLOCKS = ((EL + 2 * EX) * 16 + 255) / 256;  // 87500

    // launch order chosen so launch #4 (= the ncu capture slot) is k_fused
    k_count_all<<<(EL + 255) / 256, 256>>>(line_dst, g2b_dst, b2g_dst);   // 1
    k_scatter_all<<<SCAT_BLOCKS, 256>>>(x_bus, x_gen,                     // 2
                                        line_src, line_dst,
                                        g2b_src, g2b_dst,
                                        b2g_src, b2g_dst);
    k_inv<<<(NBS + 255) / 256, 256>>>();                                  // 3
    k_fused<<<BUSB + GENB, 256>>>(x_bus, x_gen,                           // 4 (ncu)
                                  Wsb[0], Wl[0], Wg2b[0], bsb[0],
                                  Wsg[0], Wb2g[0], bsg[0]);
    k_scatter_all<<<SCAT_BLOCKS, 256>>>(nullptr, nullptr,                 // 5
                                        line_src, line_dst,
                                        g2b_src, g2b_dst,
                                        b2g_src, b2g_dst);
    k_fused<<<BUSB + GENB, 256>>>(nullptr, nullptr,                       // 6
                                  Wsb[1], Wl[1], Wg2b[1], bsb[1],
                                  Wsg[1], Wb2g[1], bsg[1]);
    k_pool_all<<<300, 256>>>();                                           // 7
    k_head<<<1, 128>>>(W_h, b_h, W_o, b_o, (float*)d_out);                // 8
}